// round 12
// baseline (speedup 1.0000x reference)
#include <cuda_runtime.h>
#include <cuda_fp16.h>
#include <math.h>
#include <cstdint>

// ---------------- problem constants ----------------
#define HH 8
#define BB 8
#define LL 2048
#define MM 1024
#define DD 64
#define NPH 16384                         // tokens per head = BB*LL

// output layout (fp32, reference return order)
#define OFF_ZQ   0
#define N_ZQ     (8*512*2048)             // 8,388,608
#define OFF_LOSS (N_ZQ)
#define OFF_IDX  (N_ZQ + 1)
#define OFF_CB   (OFF_IDX + BB*HH*LL)

#define RMS_EPS  1.1920929e-07f
#define COS_EPS  1e-8f

// ---------------- device scratch (no allocs) ----------------
__device__ __align__(128) __half g_c1[HH*MM*DD];
__device__ __align__(16) float g_sums[HH*MM*DD];
__device__ float g_counts[HH*MM];
__device__ float g_loss;

// ---------------- mma / ldmatrix / cp.async helpers ----------------
__device__ __forceinline__ void mma_f16(float* d, const uint32_t* a,
                                        const uint32_t* b) {
    asm volatile(
        "mma.sync.aligned.m16n8k16.row.col.f32.f16.f16.f32 "
        "{%0,%1,%2,%3}, {%4,%5,%6,%7}, {%8,%9}, {%0,%1,%2,%3};"
        : "+f"(d[0]), "+f"(d[1]), "+f"(d[2]), "+f"(d[3])
        : "r"(a[0]), "r"(a[1]), "r"(a[2]), "r"(a[3]), "r"(b[0]), "r"(b[1]));
}
__device__ __forceinline__ void ldsm_x4(uint32_t& r0, uint32_t& r1,
                                        uint32_t& r2, uint32_t& r3,
                                        uint32_t addr) {
    asm volatile("ldmatrix.sync.aligned.m8n8.x4.shared.b16 {%0,%1,%2,%3}, [%4];"
                 : "=r"(r0), "=r"(r1), "=r"(r2), "=r"(r3) : "r"(addr));
}
__device__ __forceinline__ uint32_t smem_u32(const void* p) {
    uint32_t a;
    asm("{ .reg .u64 t; cvta.to.shared.u64 t, %1; cvt.u32.u64 %0, t; }"
        : "=r"(a) : "l"(p));
    return a;
}
#define CP16(dst, src) \
    asm volatile("cp.async.cg.shared.global [%0], [%1], 16;" \
                 :: "r"(dst), "l"(src))
#define CP_COMMIT() asm volatile("cp.async.commit_group;" ::: "memory")
#define CP_WAIT(n)  asm volatile("cp.async.wait_group %0;" :: "n"(n) : "memory")

__device__ __forceinline__ uint32_t pack2h(__half lo, __half hi) {
    __half2 t;
    t.x = lo; t.y = hi;
    return *(uint32_t*)&t;
}

// top-4 helpers
__device__ __forceinline__ void upd4(float* bv, int* bi, float v, int idx) {
    if (v <= bv[3]) return;
    if (v > bv[0]) {
        bv[3] = bv[2]; bi[3] = bi[2];
        bv[2] = bv[1]; bi[2] = bi[1];
        bv[1] = bv[0]; bi[1] = bi[0];
        bv[0] = v; bi[0] = idx;
    } else if (v > bv[1]) {
        bv[3] = bv[2]; bi[3] = bi[2];
        bv[2] = bv[1]; bi[2] = bi[1];
        bv[1] = v; bi[1] = idx;
    } else if (v > bv[2]) {
        bv[3] = bv[2]; bi[3] = bi[2];
        bv[2] = v; bi[2] = idx;
    } else {
        bv[3] = v; bi[3] = idx;
    }
}
__device__ __forceinline__ bool better(float av, int ai, float bv, int bi) {
    return av > bv || (av == bv && ai < bi);
}

// ---------------------------------------------------------------------------
// K0: prep — fp16 codebook copy; zero scratch
// ---------------------------------------------------------------------------
__global__ __launch_bounds__(256)
void vq_prep(const float* __restrict__ cb) {
    int i = blockIdx.x * 256 + threadIdx.x;   // < 524288
    g_c1[i] = __float2half(cb[i]);
    g_sums[i] = 0.0f;
    if (i < HH * MM) g_counts[i] = 0.0f;
    if (i == 0) g_loss = 0.0f;
}

// ---------------------------------------------------------------------------
// K1: fused — z stage + fp16 HMMA phase-1 + top-4 + exact fp32 rescore
//     + coalesced epilogue. CTA = (head, 128 tokens). 8 warps, 16 rows each.
//     B in 128-code tiles, 3-stage cp.async pipeline.
// ---------------------------------------------------------------------------
#define BPITCH 144
#define BTILE  (128 * BPITCH)             // 18432 B per stage
#define ZPITCH 132
#define ZQPITCH 129
#define SM_Z     (3 * BTILE)              // 55296 (zq staging reuses [0,55296))
#define SM_CANDS (SM_Z + 64 * ZPITCH * 4) // 89088
#define SM_SIDX  (SM_CANDS + 2048)        // 91136
#define SM_WSUM  (SM_SIDX + 512)          // 91648
#define SM_TOTAL (SM_WSUM + 32)           // 91680  -> 2 CTAs/SM

__global__ __launch_bounds__(256, 2)
void vq_gemm(const float* __restrict__ z, const float* __restrict__ cb,
             float* __restrict__ out) {
    extern __shared__ char smem[];
    float* zsh = (float*)(smem + SM_Z);
    int4* cands = (int4*)(smem + SM_CANDS);
    int* sidx = (int*)(smem + SM_SIDX);
    float* wsum = (float*)(smem + SM_WSUM);
    const uint32_t sb = smem_u32(smem);

    const int h  = blockIdx.y;
    const int n0 = blockIdx.x * 128;
    const int b  = n0 >> 11;              // batch
    const int l0 = n0 & 2047;             // l offset within batch
    const int tid = threadIdx.x;
    const int w = tid >> 5, l = tid & 31;
    const int gq = l >> 2, tq = l & 3;

    // ---- prologue: cp.async z tile, then B tiles 0 and 1 ----
    const float* zb = z + ((size_t)b * 512 + (size_t)h * 64) * 2048 + l0;
    for (int i = tid; i < 64 * 32; i += 256) {
        int k = i >> 5, c = i & 31;
        CP16(sb + SM_Z + (k * ZPITCH + c * 4) * 4,
             (const char*)(zb + (size_t)k * 2048 + c * 4));
    }
    CP_COMMIT();
#pragma unroll
    for (int t = 0; t < 2; t++) {
        for (int j = tid; j < 1024; j += 256) {
            int r = j >> 3, c = j & 7;
            CP16(sb + t * BTILE + r * BPITCH + c * 16,
                 (const char*)(g_c1 + ((size_t)h * MM + t * 128 + r) * DD)
                     + c * 16);
        }
        CP_COMMIT();
    }

    CP_WAIT(2);              // z ready (B tiles 0/1 may still be in flight)
    __syncthreads();

    // ---- build A fragments in regs: 4 ksteps x 4 regs (fp16 of z) ----
    uint32_t afr[4][4];
    {
        const int r0 = w * 16 + gq;
#pragma unroll
        for (int ks = 0; ks < 4; ks++)
#pragma unroll
            for (int half = 0; half < 2; half++)
#pragma unroll
                for (int rr = 0; rr < 2; rr++) {
                    int k0 = ks * 16 + 2 * tq + half * 8;
                    int row = r0 + rr * 8;
                    __half a0 = __float2half(zsh[k0 * ZPITCH + row]);
                    __half a1 = __float2half(zsh[(k0 + 1) * ZPITCH + row]);
                    afr[ks][rr + half * 2] = pack2h(a0, a1);
                }
    }

    // per-thread top-4 for the two row outputs (row rl and rl+8)
    float bv0[4] = {-3.0e38f, -3.0e38f, -3.0e38f, -3.0e38f};
    float bv1[4] = {-3.0e38f, -3.0e38f, -3.0e38f, -3.0e38f};
    int   bi0[4] = {0, 1, 2, 3}, bi1[4] = {0, 1, 2, 3};

    const uint32_t laneoff = (((l >> 4) * 8 + (l & 7)) * BPITCH) +
                             (((l >> 3) & 1) * 16);

    for (int mt = 0; mt < 8; mt++) {
        if (mt == 7) { CP_WAIT(0); } else { CP_WAIT(1); }
        __syncthreads();

        if (mt < 6) {                      // prefetch tile mt+2
            uint32_t dstb = sb + ((mt + 2) % 3) * BTILE;
            for (int j = tid; j < 1024; j += 256) {
                int r = j >> 3, c = j & 7;
                CP16(dstb + r * BPITCH + c * 16,
                     (const char*)(g_c1 +
                                   ((size_t)h * MM + (mt + 2) * 128 + r) * DD)
                         + c * 16);
            }
            CP_COMMIT();
        }

        const uint32_t bbase = sb + (mt % 3) * BTILE + laneoff;

#pragma unroll
        for (int sg = 0; sg < 4; sg++) {
            float acc[4][4];
#pragma unroll
            for (int s = 0; s < 4; s++)
#pragma unroll
                for (int i = 0; i < 4; i++) acc[s][i] = 0.0f;

#pragma unroll
            for (int ks = 0; ks < 4; ks++) {
                uint32_t bfr[4][2];
#pragma unroll
                for (int sp = 0; sp < 2; sp++) {
                    uint32_t addr = bbase + (sg * 32 + sp * 16) * BPITCH +
                                    ks * 32;
                    ldsm_x4(bfr[sp * 2][0], bfr[sp * 2][1],
                            bfr[sp * 2 + 1][0], bfr[sp * 2 + 1][1], addr);
                }
#pragma unroll
                for (int s = 0; s < 4; s++)
                    mma_f16(acc[s], afr[ks], bfr[s]);
            }

            // top-4 update (ascending index scan)
#pragma unroll
            for (int s = 0; s < 4; s++) {
                int nb = mt * 128 + sg * 32 + s * 8 + 2 * tq;
                upd4(bv0, bi0, acc[s][0], nb);
                upd4(bv0, bi0, acc[s][1], nb + 1);
                upd4(bv1, bi1, acc[s][2], nb);
                upd4(bv1, bi1, acc[s][3], nb + 1);
            }
        }
    }

    // ---- merge top-4 across the 4 lanes covering each row ----
#pragma unroll
    for (int off = 1; off <= 2; off <<= 1) {
#pragma unroll
        for (int q = 0; q < 4; q++) {
            float ov = __shfl_xor_sync(0xFFFFFFFFu, bv0[q], off);
            int   oi = __shfl_xor_sync(0xFFFFFFFFu, bi0[q], off);
            upd4(bv0, bi0, ov, oi);
            ov = __shfl_xor_sync(0xFFFFFFFFu, bv1[q], off);
            oi = __shfl_xor_sync(0xFFFFFFFFu, bi1[q], off);
            upd4(bv1, bi1, ov, oi);
        }
    }

    if (tq == 0) {
        int rl = w * 16 + gq;
        cands[rl] = make_int4(bi0[0], bi0[1], bi0[2], bi0[3]);
        cands[rl + 8] = make_int4(bi1[0], bi1[1], bi1[2], bi1[3]);
    }
    __syncthreads();

    // ---- exact fp32 rescore of the 4 candidates per row ----
    const float* cbh = cb + (size_t)h * MM * DD;
    {
        int row = tid >> 1, c = tid & 1;
        int4 cc = cands[row];
        int ma = c ? cc.z : cc.x;
        int mb = c ? cc.w : cc.y;
        const float4* ra = (const float4*)(cbh + (size_t)ma * DD);
        const float4* rb = (const float4*)(cbh + (size_t)mb * DD);
        float da = 0.0f, db = 0.0f;
#pragma unroll
        for (int k4 = 0; k4 < 16; k4++) {
            float4 ca = __ldg(ra + k4);
            float4 cbv = __ldg(rb + k4);
            float z0 = zsh[(4 * k4) * ZPITCH + row];
            float z1 = zsh[(4 * k4 + 1) * ZPITCH + row];
            float z2 = zsh[(4 * k4 + 2) * ZPITCH + row];
            float z3 = zsh[(4 * k4 + 3) * ZPITCH + row];
            da += z0 * ca.x + z1 * ca.y + z2 * ca.z + z3 * ca.w;
            db += z0 * cbv.x + z1 * cbv.y + z2 * cbv.z + z3 * cbv.w;
        }
        float bvv = da; int bii = ma;
        if (better(db, mb, da, ma)) { bvv = db; bii = mb; }
        float ov = __shfl_xor_sync(0xFFFFFFFFu, bvv, 1);
        int   oi = __shfl_xor_sync(0xFFFFFFFFu, bii, 1);
        if (c == 0) {
            int win = better(bvv, bii, ov, oi) ? bii : oi;
            sidx[row] = win;
            out[OFF_IDX + ((size_t)(b * HH + h)) * LL + l0 + row] = (float)win;
            atomicAdd(&g_counts[h * MM + win], 1.0f);
        }
    }
    __syncthreads();

    // ---- epilogue phase A: coalesced cb gather -> smem zq stage + loss ----
    float* zqs = (float*)smem;                   // reuse dead B stages
    float lsum = 0.0f;
    for (int i = tid; i < 128 * 16; i += 256) {
        int ll = i >> 4, kg = i & 15;            // 16 threads cover one cb row
        int m = sidx[ll];
        float4 cv = __ldg((const float4*)(cbh + (size_t)m * DD + 4 * kg));
        zqs[(4 * kg) * ZQPITCH + ll] = cv.x;
        zqs[(4 * kg + 1) * ZQPITCH + ll] = cv.y;
        zqs[(4 * kg + 2) * ZQPITCH + ll] = cv.z;
        zqs[(4 * kg + 3) * ZQPITCH + ll] = cv.w;
        float d0 = zsh[(4 * kg) * ZPITCH + ll] - cv.x;
        float d1 = zsh[(4 * kg + 1) * ZPITCH + ll] - cv.y;
        float d2 = zsh[(4 * kg + 2) * ZPITCH + ll] - cv.z;
        float d3 = zsh[(4 * kg + 3) * ZPITCH + ll] - cv.w;
        lsum += d0 * d0 + d1 * d1 + d2 * d2 + d3 * d3;
    }

    // segment sums: thread = (ll, 4k-group) -> float4 atomic
    for (int i = tid; i < 128 * 16; i += 256) {
        int ll = i >> 4, kg = i & 15;
        int m = sidx[ll];
        float4 v = make_float4(zsh[(4 * kg) * ZPITCH + ll],
                               zsh[(4 * kg + 1) * ZPITCH + ll],
                               zsh[(4 * kg + 2) * ZPITCH + ll],
                               zsh[(4 * kg + 3) * ZPITCH + ll]);
        atomicAdd((float4*)&g_sums[((size_t)(h * MM + m)) * DD + 4 * kg], v);
    }
    __syncthreads();

    // ---- epilogue phase B: coalesced zq write ----
    float* zqb = out + OFF_ZQ + ((size_t)b * 512 + (size_t)h * 64) * 2048 + l0;
    for (int i = tid; i < 64 * 128; i += 256) {
        int k = i >> 7, ll = i & 127;
        zqb[(size_t)k * 2048 + ll] = zqs[k * ZQPITCH + ll];
    }

    // loss reduce
#pragma unroll
    for (int off = 16; off > 0; off >>= 1)
        lsum += __shfl_xor_sync(0xFFFFFFFFu, lsum, off);
    if (l == 0) wsum[w] = lsum;
    __syncthreads();
    if (tid == 0) {
        float s = 0.0f;
#pragma unroll
        for (int ww = 0; ww < 8; ww++) s += wsum[ww];
        atomicAdd(&g_loss, s);
    }
}

// ---------------------------------------------------------------------------
// K2: EMA slerp codebook update + loss finalize. One warp per (h, m).
// ---------------------------------------------------------------------------
__global__ __launch_bounds__(256)
void vq_update(const float* __restrict__ cb, float* __restrict__ out) {
    int gid = blockIdx.x * blockDim.x + threadIdx.x;
    int gw = gid >> 5;
    int lane = threadIdx.x & 31;

    if (gw == 0 && lane == 0)
        out[OFF_LOSS] = 1.25f * g_loss / 8388608.0f;

    if (gw >= HH * MM) return;
    int h = gw >> 10;
    int m = gw & (MM - 1);

    const float* hi = cb + ((size_t)h * MM + m) * DD;
    float h0 = hi[lane], h1 = hi[lane + 32];
    float cnt = g_counts[h * MM + m];
    float o0 = h0, o1 = h1;

    if (cnt > 0.0f) {
        float inv = 1.0f / fmaxf(cnt, 1.0f);
        const float* sp = g_sums + ((size_t)h * MM + m) * DD;
        float s0 = sp[lane] * inv, s1 = sp[lane + 32] * inv;

        float dot = s0 * h0 + s1 * h1;
        float nl = s0 * s0 + s1 * s1;
        float nh = h0 * h0 + h1 * h1;
#pragma unroll
        for (int off = 16; off > 0; off >>= 1) {
            dot += __shfl_xor_sync(0xFFFFFFFFu, dot, off);
            nl  += __shfl_xor_sync(0xFFFFFFFFu, nl, off);
            nh  += __shfl_xor_sync(0xFFFFFFFFu, nh, off);
        }
        float c = dot / fmaxf(sqrtf(nl) * sqrtf(nh), COS_EPS);
        c = fminf(fmaxf(c, -1.0f + 1e-7f), 1.0f - 1e-7f);
        float om = acosf(c);
        float so = sinf(om);
        float wl = sinf(0.01f * om) / so;
        float wh = sinf(0.99f * om) / so;
        float r0 = s0 * wl + h0 * wh;
        float r1 = s1 * wl + h1 * wh;

        float ms = r0 * r0 + r1 * r1;
#pragma unroll
        for (int off = 16; off > 0; off >>= 1)
            ms += __shfl_xor_sync(0xFFFFFFFFu, ms, off);
        float rinv = rsqrtf(ms * (1.0f / 64.0f) + RMS_EPS);
        o0 = r0 * rinv;
        o1 = r1 * rinv;
    }

    size_t ob = OFF_CB + ((size_t)h * MM + m) * DD;
    out[ob + lane] = o0;
    out[ob + lane + 32] = o1;
}

// ---------------------------------------------------------------------------
extern "C" void kernel_launch(void* const* d_in, const int* in_sizes, int n_in,
                              void* d_out, int out_size) {
    const float* z  = (const float*)d_in[0];
    const float* cb = (const float*)d_in[1];
    float* out = (float*)d_out;

    cudaFuncSetAttribute(vq_gemm, cudaFuncAttributeMaxDynamicSharedMemorySize,
                         SM_TOTAL);

    vq_prep<<<2048, 256>>>(cb);
    vq_gemm<<<dim3(128, 8), 256, SM_TOTAL>>>(z, cb, out);
    vq_update<<<1024, 256>>>(cb, out);
}

// round 15
// speedup vs baseline: 1.0404x; 1.0404x over previous
#include <cuda_runtime.h>
#include <cuda_fp16.h>
#include <math.h>
#include <cstdint>

// ---------------- problem constants ----------------
#define HH 8
#define BB 8
#define LL 2048
#define MM 1024
#define DD 64
#define NPH 16384                         // tokens per head = BB*LL

// output layout (fp32, reference return order)
#define OFF_ZQ   0
#define N_ZQ     (8*512*2048)             // 8,388,608
#define OFF_LOSS (N_ZQ)
#define OFF_IDX  (N_ZQ + 1)
#define OFF_CB   (OFF_IDX + BB*HH*LL)

#define RMS_EPS  1.1920929e-07f
#define COS_EPS  1e-8f

// ---------------- device scratch (no allocs) ----------------
__device__ __align__(128) __half g_c1[HH*MM*DD];
__device__ __align__(16) float g_sums[HH*MM*DD];
__device__ float g_counts[HH*MM];
__device__ float g_loss;

// ---------------- mma / ldmatrix / cp.async helpers ----------------
__device__ __forceinline__ void mma_f16(float* d, const uint32_t* a,
                                        const uint32_t* b) {
    asm volatile(
        "mma.sync.aligned.m16n8k16.row.col.f32.f16.f16.f32 "
        "{%0,%1,%2,%3}, {%4,%5,%6,%7}, {%8,%9}, {%0,%1,%2,%3};"
        : "+f"(d[0]), "+f"(d[1]), "+f"(d[2]), "+f"(d[3])
        : "r"(a[0]), "r"(a[1]), "r"(a[2]), "r"(a[3]), "r"(b[0]), "r"(b[1]));
}
__device__ __forceinline__ void ldsm_x4(uint32_t& r0, uint32_t& r1,
                                        uint32_t& r2, uint32_t& r3,
                                        uint32_t addr) {
    asm volatile("ldmatrix.sync.aligned.m8n8.x4.shared.b16 {%0,%1,%2,%3}, [%4];"
                 : "=r"(r0), "=r"(r1), "=r"(r2), "=r"(r3) : "r"(addr));
}
__device__ __forceinline__ uint32_t smem_u32(const void* p) {
    uint32_t a;
    asm("{ .reg .u64 t; cvta.to.shared.u64 t, %1; cvt.u32.u64 %0, t; }"
        : "=r"(a) : "l"(p));
    return a;
}
#define CP16(dst, src) \
    asm volatile("cp.async.cg.shared.global [%0], [%1], 16;" \
                 :: "r"(dst), "l"(src))
#define CP_COMMIT() asm volatile("cp.async.commit_group;" ::: "memory")
#define CP_WAIT(n)  asm volatile("cp.async.wait_group %0;" :: "n"(n) : "memory")

__device__ __forceinline__ uint32_t pack2h(__half lo, __half hi) {
    __half2 t;
    t.x = lo; t.y = hi;
    return *(uint32_t*)&t;
}

// top-4 helpers
__device__ __forceinline__ void upd4(float* bv, int* bi, float v, int idx) {
    if (v <= bv[3]) return;
    if (v > bv[0]) {
        bv[3] = bv[2]; bi[3] = bi[2];
        bv[2] = bv[1]; bi[2] = bi[1];
        bv[1] = bv[0]; bi[1] = bi[0];
        bv[0] = v; bi[0] = idx;
    } else if (v > bv[1]) {
        bv[3] = bv[2]; bi[3] = bi[2];
        bv[2] = bv[1]; bi[2] = bi[1];
        bv[1] = v; bi[1] = idx;
    } else if (v > bv[2]) {
        bv[3] = bv[2]; bi[3] = bi[2];
        bv[2] = v; bi[2] = idx;
    } else {
        bv[3] = v; bi[3] = idx;
    }
}
__device__ __forceinline__ bool better(float av, int ai, float bv, int bi) {
    return av > bv || (av == bv && ai < bi);
}

// ---------------------------------------------------------------------------
// K0: prep — fp16 codebook copy; zero scratch
// ---------------------------------------------------------------------------
__global__ __launch_bounds__(256)
void vq_prep(const float* __restrict__ cb) {
    int i = blockIdx.x * 256 + threadIdx.x;   // < 524288
    g_c1[i] = __float2half(cb[i]);
    g_sums[i] = 0.0f;
    if (i < HH * MM) g_counts[i] = 0.0f;
    if (i == 0) g_loss = 0.0f;
}

// ---------------------------------------------------------------------------
// K1: fused — z stage + fp16 HMMA phase-1 + quad-max top-4 + exact rescore
//     of 16 candidates + coalesced epilogue. CTA = (head, 128 tokens).
//     8 warps, 16 rows each. B in 128-code tiles, 3-stage cp.async pipeline.
// ---------------------------------------------------------------------------
#define BPITCH 144
#define BTILE  (128 * BPITCH)             // 18432 B per stage
#define ZPITCH 132
#define ZQPITCH 129
#define SM_Z     (3 * BTILE)              // 55296 (zq staging reuses [0,55296))
#define SM_CANDS (SM_Z + 64 * ZPITCH * 4) // 89088
#define SM_SIDX  (SM_CANDS + 2048)        // 91136
#define SM_WSUM  (SM_SIDX + 512)          // 91648
#define SM_TOTAL (SM_WSUM + 32)           // 91680  -> 2 CTAs/SM

__global__ __launch_bounds__(256, 2)
void vq_gemm(const float* __restrict__ z, const float* __restrict__ cb,
             float* __restrict__ out) {
    extern __shared__ char smem[];
    float* zsh = (float*)(smem + SM_Z);
    int4* cands = (int4*)(smem + SM_CANDS);
    int* sidx = (int*)(smem + SM_SIDX);
    float* wsum = (float*)(smem + SM_WSUM);
    const uint32_t sb = smem_u32(smem);

    const int h  = blockIdx.y;
    const int n0 = blockIdx.x * 128;
    const int b  = n0 >> 11;              // batch
    const int l0 = n0 & 2047;             // l offset within batch
    const int tid = threadIdx.x;
    const int w = tid >> 5, l = tid & 31;
    const int gq = l >> 2, tq = l & 3;

    // ---- prologue: cp.async z tile, then B tiles 0 and 1 ----
    const float* zb = z + ((size_t)b * 512 + (size_t)h * 64) * 2048 + l0;
    for (int i = tid; i < 64 * 32; i += 256) {
        int k = i >> 5, c = i & 31;
        CP16(sb + SM_Z + (k * ZPITCH + c * 4) * 4,
             (const char*)(zb + (size_t)k * 2048 + c * 4));
    }
    CP_COMMIT();
#pragma unroll
    for (int t = 0; t < 2; t++) {
        for (int j = tid; j < 1024; j += 256) {
            int r = j >> 3, c = j & 7;
            CP16(sb + t * BTILE + r * BPITCH + c * 16,
                 (const char*)(g_c1 + ((size_t)h * MM + t * 128 + r) * DD)
                     + c * 16);
        }
        CP_COMMIT();
    }

    CP_WAIT(2);              // z ready (B tiles 0/1 may still be in flight)
    __syncthreads();

    // ---- build A fragments in regs: 4 ksteps x 4 regs (fp16 of z) ----
    uint32_t afr[4][4];
    {
        const int r0 = w * 16 + gq;
#pragma unroll
        for (int ks = 0; ks < 4; ks++)
#pragma unroll
            for (int half = 0; half < 2; half++)
#pragma unroll
                for (int rr = 0; rr < 2; rr++) {
                    int k0 = ks * 16 + 2 * tq + half * 8;
                    int row = r0 + rr * 8;
                    __half a0 = __float2half(zsh[k0 * ZPITCH + row]);
                    __half a1 = __float2half(zsh[(k0 + 1) * ZPITCH + row]);
                    afr[ks][rr + half * 2] = pack2h(a0, a1);
                }
    }

    // per-thread top-4 QUADS for the two row outputs (rows rl and rl+8).
    // A quad with base c covers codes {c, c+8, c+16, c+24}.
    float bv0[4] = {-3.0e38f, -3.0e38f, -3.0e38f, -3.0e38f};
    float bv1[4] = {-3.0e38f, -3.0e38f, -3.0e38f, -3.0e38f};
    int   bi0[4] = {0, 1, 2, 3}, bi1[4] = {0, 1, 2, 3};

    const uint32_t laneoff = (((l >> 4) * 8 + (l & 7)) * BPITCH) +
                             (((l >> 3) & 1) * 16);

    for (int mt = 0; mt < 8; mt++) {
        if (mt == 7) { CP_WAIT(0); } else { CP_WAIT(1); }
        __syncthreads();

        if (mt < 6) {                      // prefetch tile mt+2
            uint32_t dstb = sb + ((mt + 2) % 3) * BTILE;
            for (int j = tid; j < 1024; j += 256) {
                int r = j >> 3, c = j & 7;
                CP16(dstb + r * BPITCH + c * 16,
                     (const char*)(g_c1 +
                                   ((size_t)h * MM + (mt + 2) * 128 + r) * DD)
                         + c * 16);
            }
            CP_COMMIT();
        }

        const uint32_t bbase = sb + (mt % 3) * BTILE + laneoff;

#pragma unroll
        for (int sg = 0; sg < 4; sg++) {
            float acc[4][4];
#pragma unroll
            for (int s = 0; s < 4; s++)
#pragma unroll
                for (int i = 0; i < 4; i++) acc[s][i] = 0.0f;

#pragma unroll
            for (int ks = 0; ks < 4; ks++) {
                uint32_t bfr[4][2];
#pragma unroll
                for (int sp = 0; sp < 2; sp++) {
                    uint32_t addr = bbase + (sg * 32 + sp * 16) * BPITCH +
                                    ks * 32;
                    ldsm_x4(bfr[sp * 2][0], bfr[sp * 2][1],
                            bfr[sp * 2 + 1][0], bfr[sp * 2 + 1][1], addr);
                }
#pragma unroll
                for (int s = 0; s < 4; s++)
                    mma_f16(acc[s], afr[ks], bfr[s]);
            }

            // quad-max screening: 4 fmax-trees, then 4 upd4 (vs 16)
            {
                float m0 = fmaxf(fmaxf(acc[0][0], acc[1][0]),
                                 fmaxf(acc[2][0], acc[3][0]));
                float m1 = fmaxf(fmaxf(acc[0][1], acc[1][1]),
                                 fmaxf(acc[2][1], acc[3][1]));
                float m2 = fmaxf(fmaxf(acc[0][2], acc[1][2]),
                                 fmaxf(acc[2][2], acc[3][2]));
                float m3 = fmaxf(fmaxf(acc[0][3], acc[1][3]),
                                 fmaxf(acc[2][3], acc[3][3]));
                int cbase = mt * 128 + sg * 32 + 2 * tq;
                upd4(bv0, bi0, m0, cbase);
                upd4(bv0, bi0, m1, cbase + 1);
                upd4(bv1, bi1, m2, cbase);
                upd4(bv1, bi1, m3, cbase + 1);
            }
        }
    }

    // ---- merge top-4 quads across the 4 lanes covering each row ----
#pragma unroll
    for (int off = 1; off <= 2; off <<= 1) {
#pragma unroll
        for (int q = 0; q < 4; q++) {
            float ov = __shfl_xor_sync(0xFFFFFFFFu, bv0[q], off);
            int   oi = __shfl_xor_sync(0xFFFFFFFFu, bi0[q], off);
            upd4(bv0, bi0, ov, oi);
            ov = __shfl_xor_sync(0xFFFFFFFFu, bv1[q], off);
            oi = __shfl_xor_sync(0xFFFFFFFFu, bi1[q], off);
            upd4(bv1, bi1, ov, oi);
        }
    }

    if (tq == 0) {
        int rl = w * 16 + gq;
        cands[rl] = make_int4(bi0[0], bi0[1], bi0[2], bi0[3]);
        cands[rl + 8] = make_int4(bi1[0], bi1[1], bi1[2], bi1[3]);
    }
    __syncthreads();

    // ---- exact fp32 rescore of 16 candidates (4 quads x 4 codes) / row ----
    const float* cbh = cb + (size_t)h * MM * DD;
    {
        int row = tid >> 1, half = tid & 1;
        int4 q = cands[row];
        int base0 = half ? q.z : q.x;     // this thread rescans 2 quads
        int base1 = half ? q.w : q.y;
        float dacc[8];
#pragma unroll
        for (int j = 0; j < 8; j++) dacc[j] = 0.0f;
#pragma unroll
        for (int k4 = 0; k4 < 16; k4++) {
            float z0 = zsh[(4 * k4) * ZPITCH + row];
            float z1 = zsh[(4 * k4 + 1) * ZPITCH + row];
            float z2 = zsh[(4 * k4 + 2) * ZPITCH + row];
            float z3 = zsh[(4 * k4 + 3) * ZPITCH + row];
#pragma unroll
            for (int j = 0; j < 4; j++) {
                float4 ca = __ldg((const float4*)(cbh +
                                  (size_t)(base0 + 8 * j) * DD + 4 * k4));
                dacc[j] += z0 * ca.x + z1 * ca.y + z2 * ca.z + z3 * ca.w;
            }
#pragma unroll
            for (int j = 0; j < 4; j++) {
                float4 ca = __ldg((const float4*)(cbh +
                                  (size_t)(base1 + 8 * j) * DD + 4 * k4));
                dacc[4 + j] += z0 * ca.x + z1 * ca.y + z2 * ca.z + z3 * ca.w;
            }
        }
        float bvv = dacc[0]; int bii = base0;
#pragma unroll
        for (int j = 1; j < 4; j++)
            if (better(dacc[j], base0 + 8 * j, bvv, bii)) {
                bvv = dacc[j]; bii = base0 + 8 * j;
            }
#pragma unroll
        for (int j = 0; j < 4; j++)
            if (better(dacc[4 + j], base1 + 8 * j, bvv, bii)) {
                bvv = dacc[4 + j]; bii = base1 + 8 * j;
            }
        float ov = __shfl_xor_sync(0xFFFFFFFFu, bvv, 1);
        int   oi = __shfl_xor_sync(0xFFFFFFFFu, bii, 1);
        if (half == 0) {
            int win = better(bvv, bii, ov, oi) ? bii : oi;
            sidx[row] = win;
            out[OFF_IDX + ((size_t)(b * HH + h)) * LL + l0 + row] = (float)win;
            atomicAdd(&g_counts[h * MM + win], 1.0f);
        }
    }
    __syncthreads();

    // ---- epilogue phase A: coalesced cb gather -> smem zq stage + loss ----
    float* zqs = (float*)smem;                   // reuse dead B stages
    float lsum = 0.0f;
    for (int i = tid; i < 128 * 16; i += 256) {
        int ll = i >> 4, kg = i & 15;            // 16 threads cover one cb row
        int m = sidx[ll];
        float4 cv = __ldg((const float4*)(cbh + (size_t)m * DD + 4 * kg));
        zqs[(4 * kg) * ZQPITCH + ll] = cv.x;
        zqs[(4 * kg + 1) * ZQPITCH + ll] = cv.y;
        zqs[(4 * kg + 2) * ZQPITCH + ll] = cv.z;
        zqs[(4 * kg + 3) * ZQPITCH + ll] = cv.w;
        float d0 = zsh[(4 * kg) * ZPITCH + ll] - cv.x;
        float d1 = zsh[(4 * kg + 1) * ZPITCH + ll] - cv.y;
        float d2 = zsh[(4 * kg + 2) * ZPITCH + ll] - cv.z;
        float d3 = zsh[(4 * kg + 3) * ZPITCH + ll] - cv.w;
        lsum += d0 * d0 + d1 * d1 + d2 * d2 + d3 * d3;
    }

    // segment sums: thread = (ll, 4k-group) -> float4 atomic
    for (int i = tid; i < 128 * 16; i += 256) {
        int ll = i >> 4, kg = i & 15;
        int m = sidx[ll];
        float4 v = make_float4(zsh[(4 * kg) * ZPITCH + ll],
                               zsh[(4 * kg + 1) * ZPITCH + ll],
                               zsh[(4 * kg + 2) * ZPITCH + ll],
                               zsh[(4 * kg + 3) * ZPITCH + ll]);
        atomicAdd((float4*)&g_sums[((size_t)(h * MM + m)) * DD + 4 * kg], v);
    }
    __syncthreads();

    // ---- epilogue phase B: coalesced zq write ----
    float* zqb = out + OFF_ZQ + ((size_t)b * 512 + (size_t)h * 64) * 2048 + l0;
    for (int i = tid; i < 64 * 128; i += 256) {
        int k = i >> 7, ll = i & 127;
        zqb[(size_t)k * 2048 + ll] = zqs[k * ZQPITCH + ll];
    }

    // loss reduce
#pragma unroll
    for (int off = 16; off > 0; off >>= 1)
        lsum += __shfl_xor_sync(0xFFFFFFFFu, lsum, off);
    if (l == 0) wsum[w] = lsum;
    __syncthreads();
    if (tid == 0) {
        float s = 0.0f;
#pragma unroll
        for (int ww = 0; ww < 8; ww++) s += wsum[ww];
        atomicAdd(&g_loss, s);
    }
}

// ---------------------------------------------------------------------------
// K2: EMA slerp codebook update + loss finalize. One warp per (h, m).
// ---------------------------------------------------------------------------
__global__ __launch_bounds__(256)
void vq_update(const float* __restrict__ cb, float* __restrict__ out) {
    int gid = blockIdx.x * blockDim.x + threadIdx.x;
    int gw = gid >> 5;
    int lane = threadIdx.x & 31;

    if (gw == 0 && lane == 0)
        out[OFF_LOSS] = 1.25f * g_loss / 8388608.0f;

    if (gw >= HH * MM) return;
    int h = gw >> 10;
    int m = gw & (MM - 1);

    const float* hi = cb + ((size_t)h * MM + m) * DD;
    float h0 = hi[lane], h1 = hi[lane + 32];
    float cnt = g_counts[h * MM + m];
    float o0 = h0, o1 = h1;

    if (cnt > 0.0f) {
        float inv = 1.0f / fmaxf(cnt, 1.0f);
        const float* sp = g_sums + ((size_t)h * MM + m) * DD;
        float s0 = sp[lane] * inv, s1 = sp[lane + 32] * inv;

        float dot = s0 * h0 + s1 * h1;
        float nl = s0 * s0 + s1 * s1;
        float nh = h0 * h0 + h1 * h1;
#pragma unroll
        for (int off = 16; off > 0; off >>= 1) {
            dot += __shfl_xor_sync(0xFFFFFFFFu, dot, off);
            nl  += __shfl_xor_sync(0xFFFFFFFFu, nl, off);
            nh  += __shfl_xor_sync(0xFFFFFFFFu, nh, off);
        }
        float c = dot / fmaxf(sqrtf(nl) * sqrtf(nh), COS_EPS);
        c = fminf(fmaxf(c, -1.0f + 1e-7f), 1.0f - 1e-7f);
        float om = acosf(c);
        float so = sinf(om);
        float wl = sinf(0.01f * om) / so;
        float wh = sinf(0.99f * om) / so;
        float r0 = s0 * wl + h0 * wh;
        float r1 = s1 * wl + h1 * wh;

        float ms = r0 * r0 + r1 * r1;
#pragma unroll
        for (int off = 16; off > 0; off >>= 1)
            ms += __shfl_xor_sync(0xFFFFFFFFu, ms, off);
        float rinv = rsqrtf(ms * (1.0f / 64.0f) + RMS_EPS);
        o0 = r0 * rinv;
        o1 = r1 * rinv;
    }

    size_t ob = OFF_CB + ((size_t)h * MM + m) * DD;
    out[ob + lane] = o0;
    out[ob + lane + 32] = o1;
}

// ---------------------------------------------------------------------------
extern "C" void kernel_launch(void* const* d_in, const int* in_sizes, int n_in,
                              void* d_out, int out_size) {
    const float* z  = (const float*)d_in[0];
    const float* cb = (const float*)d_in[1];
    float* out = (float*)d_out;

    cudaFuncSetAttribute(vq_gemm, cudaFuncAttributeMaxDynamicSharedMemorySize,
                         SM_TOTAL);

    vq_prep<<<2048, 256>>>(cb);
    vq_gemm<<<dim3(128, 8), 256, SM_TOTAL>>>(z, cb, out);
    vq_update<<<1024, 256>>>(cb, out);
}

// round 16
// speedup vs baseline: 1.0800x; 1.0380x over previous
#include <cuda_runtime.h>
#include <cuda_fp16.h>
#include <math.h>
#include <cstdint>

// ---------------- problem constants ----------------
#define HH 8
#define BB 8
#define LL 2048
#define MM 1024
#define DD 64
#define NPH 16384                         // tokens per head = BB*LL

// output layout (fp32, reference return order)
#define OFF_ZQ   0
#define N_ZQ     (8*512*2048)             // 8,388,608
#define OFF_LOSS (N_ZQ)
#define OFF_IDX  (N_ZQ + 1)
#define OFF_CB   (OFF_IDX + BB*HH*LL)

#define RMS_EPS  1.1920929e-07f
#define COS_EPS  1e-8f

// ---------------- device scratch (no allocs) ----------------
__device__ __align__(128) __half g_c1[HH*MM*DD];
__device__ __align__(16) float g_sums[HH*MM*DD];
__device__ float g_counts[HH*MM];
__device__ float g_loss;

// ---------------- mma / ldmatrix / cp.async helpers ----------------
__device__ __forceinline__ void mma_f16(float* d, const uint32_t* a,
                                        const uint32_t* b) {
    asm volatile(
        "mma.sync.aligned.m16n8k16.row.col.f32.f16.f16.f32 "
        "{%0,%1,%2,%3}, {%4,%5,%6,%7}, {%8,%9}, {%0,%1,%2,%3};"
        : "+f"(d[0]), "+f"(d[1]), "+f"(d[2]), "+f"(d[3])
        : "r"(a[0]), "r"(a[1]), "r"(a[2]), "r"(a[3]), "r"(b[0]), "r"(b[1]));
}
__device__ __forceinline__ void ldsm_x4(uint32_t& r0, uint32_t& r1,
                                        uint32_t& r2, uint32_t& r3,
                                        uint32_t addr) {
    asm volatile("ldmatrix.sync.aligned.m8n8.x4.shared.b16 {%0,%1,%2,%3}, [%4];"
                 : "=r"(r0), "=r"(r1), "=r"(r2), "=r"(r3) : "r"(addr));
}
__device__ __forceinline__ uint32_t smem_u32(const void* p) {
    uint32_t a;
    asm("{ .reg .u64 t; cvta.to.shared.u64 t, %1; cvt.u32.u64 %0, t; }"
        : "=r"(a) : "l"(p));
    return a;
}
#define CP16(dst, src) \
    asm volatile("cp.async.cg.shared.global [%0], [%1], 16;" \
                 :: "r"(dst), "l"(src))
#define CP_COMMIT() asm volatile("cp.async.commit_group;" ::: "memory")
#define CP_WAIT(n)  asm volatile("cp.async.wait_group %0;" :: "n"(n) : "memory")

__device__ __forceinline__ uint32_t pack2h(__half lo, __half hi) {
    __half2 t;
    t.x = lo; t.y = hi;
    return *(uint32_t*)&t;
}

// top-4 helpers
__device__ __forceinline__ void upd4(float* bv, int* bi, float v, int idx) {
    if (v <= bv[3]) return;
    if (v > bv[0]) {
        bv[3] = bv[2]; bi[3] = bi[2];
        bv[2] = bv[1]; bi[2] = bi[1];
        bv[1] = bv[0]; bi[1] = bi[0];
        bv[0] = v; bi[0] = idx;
    } else if (v > bv[1]) {
        bv[3] = bv[2]; bi[3] = bi[2];
        bv[2] = bv[1]; bi[2] = bi[1];
        bv[1] = v; bi[1] = idx;
    } else if (v > bv[2]) {
        bv[3] = bv[2]; bi[3] = bi[2];
        bv[2] = v; bi[2] = idx;
    } else {
        bv[3] = v; bi[3] = idx;
    }
}
__device__ __forceinline__ bool better(float av, int ai, float bv, int bi) {
    return av > bv || (av == bv && ai < bi);
}

// ---------------------------------------------------------------------------
// K0: prep — fp16 codebook copy; zero scratch
// ---------------------------------------------------------------------------
__global__ __launch_bounds__(256)
void vq_prep(const float* __restrict__ cb) {
    int i = blockIdx.x * 256 + threadIdx.x;   // < 524288
    g_c1[i] = __float2half(cb[i]);
    g_sums[i] = 0.0f;
    if (i < HH * MM) g_counts[i] = 0.0f;
    if (i == 0) g_loss = 0.0f;
}

// ---------------------------------------------------------------------------
// K1: fused — z stage + fp16 HMMA phase-1 + quad-max top-4 + exact rescore
//     of 16 candidates + two-pass coalesced epilogue.
// CTA = (head, 128 tokens). 8 warps, 16 rows each.
// B in 64-code tiles, 3-stage cp.async pipeline. 3 CTAs/SM (64 KB smem).
// ---------------------------------------------------------------------------
#define BPITCH 144
#define BT64   (64 * BPITCH)              // 9216 B per stage
#define ZPITCH 132
#define ZQP    66                         // two-pass zq staging pitch
#define SM_Z     (3 * BT64)               // 27648 (zq staging reuses [0,27648))
#define SM_CANDS (SM_Z + 64 * ZPITCH * 4) // 61440
#define SM_SIDX  (SM_CANDS + 2048)        // 63488
#define SM_WSUM  (SM_SIDX + 512)          // 64000
#define SM_TOTAL (SM_WSUM + 32)           // 64032  -> 3 CTAs/SM
 
__global__ __launch_bounds__(256, 3)
void vq_gemm(const float* __restrict__ z, const float* __restrict__ cb,
             float* __restrict__ out) {
    extern __shared__ char smem[];
    float* zsh = (float*)(smem + SM_Z);
    int4* cands = (int4*)(smem + SM_CANDS);
    int* sidx = (int*)(smem + SM_SIDX);
    float* wsum = (float*)(smem + SM_WSUM);
    const uint32_t sb = smem_u32(smem);

    const int h  = blockIdx.y;
    const int n0 = blockIdx.x * 128;
    const int b  = n0 >> 11;              // batch
    const int l0 = n0 & 2047;             // l offset within batch
    const int tid = threadIdx.x;
    const int w = tid >> 5, l = tid & 31;
    const int gq = l >> 2, tq = l & 3;

    // ---- prologue: cp.async z tile, then B tiles 0 and 1 ----
    const float* zb = z + ((size_t)b * 512 + (size_t)h * 64) * 2048 + l0;
    for (int i = tid; i < 64 * 32; i += 256) {
        int k = i >> 5, c = i & 31;
        CP16(sb + SM_Z + (k * ZPITCH + c * 4) * 4,
             (const char*)(zb + (size_t)k * 2048 + c * 4));
    }
    CP_COMMIT();
#pragma unroll
    for (int t = 0; t < 2; t++) {
        for (int j = tid; j < 512; j += 256) {
            int r = j >> 3, c = j & 7;
            CP16(sb + t * BT64 + r * BPITCH + c * 16,
                 (const char*)(g_c1 + ((size_t)h * MM + t * 64 + r) * DD)
                     + c * 16);
        }
        CP_COMMIT();
    }

    CP_WAIT(2);              // z ready (B tiles 0/1 may still be in flight)
    __syncthreads();

    // ---- build A fragments in regs: 4 ksteps x 4 regs (fp16 of z) ----
    uint32_t afr[4][4];
    {
        const int r0 = w * 16 + gq;
#pragma unroll
        for (int ks = 0; ks < 4; ks++)
#pragma unroll
            for (int half = 0; half < 2; half++)
#pragma unroll
                for (int rr = 0; rr < 2; rr++) {
                    int k0 = ks * 16 + 2 * tq + half * 8;
                    int row = r0 + rr * 8;
                    __half a0 = __float2half(zsh[k0 * ZPITCH + row]);
                    __half a1 = __float2half(zsh[(k0 + 1) * ZPITCH + row]);
                    afr[ks][rr + half * 2] = pack2h(a0, a1);
                }
    }

    // per-thread top-4 QUADS for the two row outputs (rows rl and rl+8).
    // A quad with base c covers codes {c, c+8, c+16, c+24}.
    float bv0[4] = {-3.0e38f, -3.0e38f, -3.0e38f, -3.0e38f};
    float bv1[4] = {-3.0e38f, -3.0e38f, -3.0e38f, -3.0e38f};
    int   bi0[4] = {0, 1, 2, 3}, bi1[4] = {0, 1, 2, 3};

    const uint32_t laneoff = (((l >> 4) * 8 + (l & 7)) * BPITCH) +
                             (((l >> 3) & 1) * 16);

    for (int mt = 0; mt < 16; mt++) {
        if (mt == 15) { CP_WAIT(0); } else { CP_WAIT(1); }
        __syncthreads();

        if (mt < 14) {                     // prefetch tile mt+2
            uint32_t dstb = sb + ((mt + 2) % 3) * BT64;
            for (int j = tid; j < 512; j += 256) {
                int r = j >> 3, c = j & 7;
                CP16(dstb + r * BPITCH + c * 16,
                     (const char*)(g_c1 +
                                   ((size_t)h * MM + (mt + 2) * 64 + r) * DD)
                         + c * 16);
            }
            CP_COMMIT();
        }

        const uint32_t bbase = sb + (mt % 3) * BT64 + laneoff;

#pragma unroll
        for (int sg = 0; sg < 2; sg++) {
            float acc[4][4];
#pragma unroll
            for (int s = 0; s < 4; s++)
#pragma unroll
                for (int i = 0; i < 4; i++) acc[s][i] = 0.0f;

#pragma unroll
            for (int ks = 0; ks < 4; ks++) {
                uint32_t bfr[4][2];
#pragma unroll
                for (int sp = 0; sp < 2; sp++) {
                    uint32_t addr = bbase + (sg * 32 + sp * 16) * BPITCH +
                                    ks * 32;
                    ldsm_x4(bfr[sp * 2][0], bfr[sp * 2][1],
                            bfr[sp * 2 + 1][0], bfr[sp * 2 + 1][1], addr);
                }
#pragma unroll
                for (int s = 0; s < 4; s++)
                    mma_f16(acc[s], afr[ks], bfr[s]);
            }

            // quad-max screening: 4 fmax-trees, then 4 upd4 (vs 16)
            {
                float m0 = fmaxf(fmaxf(acc[0][0], acc[1][0]),
                                 fmaxf(acc[2][0], acc[3][0]));
                float m1 = fmaxf(fmaxf(acc[0][1], acc[1][1]),
                                 fmaxf(acc[2][1], acc[3][1]));
                float m2 = fmaxf(fmaxf(acc[0][2], acc[1][2]),
                                 fmaxf(acc[2][2], acc[3][2]));
                float m3 = fmaxf(fmaxf(acc[0][3], acc[1][3]),
                                 fmaxf(acc[2][3], acc[3][3]));
                int cbase = mt * 64 + sg * 32 + 2 * tq;
                upd4(bv0, bi0, m0, cbase);
                upd4(bv0, bi0, m1, cbase + 1);
                upd4(bv1, bi1, m2, cbase);
                upd4(bv1, bi1, m3, cbase + 1);
            }
        }
    }

    // ---- merge top-4 quads across the 4 lanes covering each row ----
#pragma unroll
    for (int off = 1; off <= 2; off <<= 1) {
#pragma unroll
        for (int q = 0; q < 4; q++) {
            float ov = __shfl_xor_sync(0xFFFFFFFFu, bv0[q], off);
            int   oi = __shfl_xor_sync(0xFFFFFFFFu, bi0[q], off);
            upd4(bv0, bi0, ov, oi);
            ov = __shfl_xor_sync(0xFFFFFFFFu, bv1[q], off);
            oi = __shfl_xor_sync(0xFFFFFFFFu, bi1[q], off);
            upd4(bv1, bi1, ov, oi);
        }
    }

    if (tq == 0) {
        int rl = w * 16 + gq;
        cands[rl] = make_int4(bi0[0], bi0[1], bi0[2], bi0[3]);
        cands[rl + 8] = make_int4(bi1[0], bi1[1], bi1[2], bi1[3]);
    }
    __syncthreads();

    // ---- exact fp32 rescore of 16 candidates (4 quads x 4 codes) / row ----
    const float* cbh = cb + (size_t)h * MM * DD;
    {
        int row = tid >> 1, half = tid & 1;
        int4 q = cands[row];
        int base0 = half ? q.z : q.x;     // this thread rescans 2 quads
        int base1 = half ? q.w : q.y;
        float dacc[8];
#pragma unroll
        for (int j = 0; j < 8; j++) dacc[j] = 0.0f;
#pragma unroll
        for (int k4 = 0; k4 < 16; k4++) {
            float z0 = zsh[(4 * k4) * ZPITCH + row];
            float z1 = zsh[(4 * k4 + 1) * ZPITCH + row];
            float z2 = zsh[(4 * k4 + 2) * ZPITCH + row];
            float z3 = zsh[(4 * k4 + 3) * ZPITCH + row];
#pragma unroll
            for (int j = 0; j < 4; j++) {
                float4 ca = __ldg((const float4*)(cbh +
                                  (size_t)(base0 + 8 * j) * DD + 4 * k4));
                dacc[j] += z0 * ca.x + z1 * ca.y + z2 * ca.z + z3 * ca.w;
            }
#pragma unroll
            for (int j = 0; j < 4; j++) {
                float4 ca = __ldg((const float4*)(cbh +
                                  (size_t)(base1 + 8 * j) * DD + 4 * k4));
                dacc[4 + j] += z0 * ca.x + z1 * ca.y + z2 * ca.z + z3 * ca.w;
            }
        }
        float bvv = dacc[0]; int bii = base0;
#pragma unroll
        for (int j = 1; j < 4; j++)
            if (better(dacc[j], base0 + 8 * j, bvv, bii)) {
                bvv = dacc[j]; bii = base0 + 8 * j;
            }
#pragma unroll
        for (int j = 0; j < 4; j++)
            if (better(dacc[4 + j], base1 + 8 * j, bvv, bii)) {
                bvv = dacc[4 + j]; bii = base1 + 8 * j;
            }
        float ov = __shfl_xor_sync(0xFFFFFFFFu, bvv, 1);
        int   oi = __shfl_xor_sync(0xFFFFFFFFu, bii, 1);
        if (half == 0) {
            int win = better(bvv, bii, ov, oi) ? bii : oi;
            sidx[row] = win;
            out[OFF_IDX + ((size_t)(b * HH + h)) * LL + l0 + row] = (float)win;
            atomicAdd(&g_counts[h * MM + win], 1.0f);
        }
    }
    __syncthreads();

    // ---- two-pass epilogue: coalesced cb gather -> smem stage -> zq write ----
    float* zqs = (float*)smem;                   // reuse dead B stages (27.6KB)
    float* zqb = out + OFF_ZQ + ((size_t)b * 512 + (size_t)h * 64) * 2048 + l0;
    float lsum = 0.0f;
#pragma unroll
    for (int p = 0; p < 2; p++) {
        // phase A: gather cb rows (coalesced), stage transposed, loss
        for (int i = tid; i < 64 * 16; i += 256) {
            int ll = i >> 4, kg = i & 15;        // ll in [0,64): token p*64+ll
            int m = sidx[p * 64 + ll];
            float4 cv = __ldg((const float4*)(cbh + (size_t)m * DD + 4 * kg));
            zqs[(4 * kg) * ZQP + ll] = cv.x;
            zqs[(4 * kg + 1) * ZQP + ll] = cv.y;
            zqs[(4 * kg + 2) * ZQP + ll] = cv.z;
            zqs[(4 * kg + 3) * ZQP + ll] = cv.w;
            int rr = p * 64 + ll;
            float d0 = zsh[(4 * kg) * ZPITCH + rr] - cv.x;
            float d1 = zsh[(4 * kg + 1) * ZPITCH + rr] - cv.y;
            float d2 = zsh[(4 * kg + 2) * ZPITCH + rr] - cv.z;
            float d3 = zsh[(4 * kg + 3) * ZPITCH + rr] - cv.w;
            lsum += d0 * d0 + d1 * d1 + d2 * d2 + d3 * d3;
        }
        __syncthreads();
        // phase B: coalesced zq write for this 64-token half
        for (int i = tid; i < 64 * 64; i += 256) {
            int k = i >> 6, ll = i & 63;
            zqb[(size_t)k * 2048 + p * 64 + ll] = zqs[k * ZQP + ll];
        }
        __syncthreads();
    }

    // segment sums: thread = (ll, 4k-group) -> float4 atomic
    for (int i = tid; i < 128 * 16; i += 256) {
        int ll = i >> 4, kg = i & 15;
        int m = sidx[ll];
        float4 v = make_float4(zsh[(4 * kg) * ZPITCH + ll],
                               zsh[(4 * kg + 1) * ZPITCH + ll],
                               zsh[(4 * kg + 2) * ZPITCH + ll],
                               zsh[(4 * kg + 3) * ZPITCH + ll]);
        atomicAdd((float4*)&g_sums[((size_t)(h * MM + m)) * DD + 4 * kg], v);
    }

    // loss reduce
#pragma unroll
    for (int off = 16; off > 0; off >>= 1)
        lsum += __shfl_xor_sync(0xFFFFFFFFu, lsum, off);
    if (l == 0) wsum[w] = lsum;
    __syncthreads();
    if (tid == 0) {
        float s = 0.0f;
#pragma unroll
        for (int ww = 0; ww < 8; ww++) s += wsum[ww];
        atomicAdd(&g_loss, s);
    }
}

// ---------------------------------------------------------------------------
// K2: EMA slerp codebook update + loss finalize. One warp per (h, m).
// ---------------------------------------------------------------------------
__global__ __launch_bounds__(256)
void vq_update(const float* __restrict__ cb, float* __restrict__ out) {
    int gid = blockIdx.x * blockDim.x + threadIdx.x;
    int gw = gid >> 5;
    int lane = threadIdx.x & 31;

    if (gw == 0 && lane == 0)
        out[OFF_LOSS] = 1.25f * g_loss / 8388608.0f;

    if (gw >= HH * MM) return;
    int h = gw >> 10;
    int m = gw & (MM - 1);

    const float* hi = cb + ((size_t)h * MM + m) * DD;
    float h0 = hi[lane], h1 = hi[lane + 32];
    float cnt = g_counts[h * MM + m];
    float o0 = h0, o1 = h1;

    if (cnt > 0.0f) {
        float inv = 1.0f / fmaxf(cnt, 1.0f);
        const float* sp = g_sums + ((size_t)h * MM + m) * DD;
        float s0 = sp[lane] * inv, s1 = sp[lane + 32] * inv;

        float dot = s0 * h0 + s1 * h1;
        float nl = s0 * s0 + s1 * s1;
        float nh = h0 * h0 + h1 * h1;
#pragma unroll
        for (int off = 16; off > 0; off >>= 1) {
            dot += __shfl_xor_sync(0xFFFFFFFFu, dot, off);
            nl  += __shfl_xor_sync(0xFFFFFFFFu, nl, off);
            nh  += __shfl_xor_sync(0xFFFFFFFFu, nh, off);
        }
        float c = dot / fmaxf(sqrtf(nl) * sqrtf(nh), COS_EPS);
        c = fminf(fmaxf(c, -1.0f + 1e-7f), 1.0f - 1e-7f);
        float om = acosf(c);
        float so = sinf(om);
        float wl = sinf(0.01f * om) / so;
        float wh = sinf(0.99f * om) / so;
        float r0 = s0 * wl + h0 * wh;
        float r1 = s1 * wl + h1 * wh;

        float ms = r0 * r0 + r1 * r1;
#pragma unroll
        for (int off = 16; off > 0; off >>= 1)
            ms += __shfl_xor_sync(0xFFFFFFFFu, ms, off);
        float rinv = rsqrtf(ms * (1.0f / 64.0f) + RMS_EPS);
        o0 = r0 * rinv;
        o1 = r1 * rinv;
    }

    size_t ob = OFF_CB + ((size_t)h * MM + m) * DD;
    out[ob + lane] = o0;
    out[ob + lane + 32] = o1;
}

// ---------------------------------------------------------------------------
extern "C" void kernel_launch(void* const* d_in, const int* in_sizes, int n_in,
                              void* d_out, int out_size) {
    const float* z  = (const float*)d_in[0];
    const float* cb = (const float*)d_in[1];
    float* out = (float*)d_out;

    cudaFuncSetAttribute(vq_gemm, cudaFuncAttributeMaxDynamicSharedMemorySize,
                         SM_TOTAL);

    vq_prep<<<2048, 256>>>(cb);
    vq_gemm<<<dim3(128, 8), 256, SM_TOTAL>>>(z, cb, out);
    vq_update<<<1024, 256>>>(cb, out);
}